// round 16
// baseline (speedup 1.0000x reference)
#include <cuda_runtime.h>
#include <cuda_fp16.h>
#include <cstdint>
#include <cstddef>

#define DIMSZ 1024
#define HD 64
#define NHEADS 16
#define BL 4096
#define MROWS 2048
#define MC 64
#define NCH (MROWS/MC)
#define SCALE_LOG2 23.083120654223414f
#define INV_SCALE  (1.0f/SCALE_LOG2)

typedef uint32_t u32;

__device__ __align__(16) __half g_k0[MROWS*HD], g_k1[MROWS*HD];
__device__ __align__(16) __half g_vT0[HD*MROWS], g_vT1[HD*MROWS];
__device__ __align__(16) __half g_q0[(size_t)BL*DIMSZ], g_q1[(size_t)BL*DIMSZ];
__device__ __align__(16) __half g_x0[(size_t)BL*DIMSZ], g_x1[(size_t)BL*DIMSZ];
__device__ __align__(16) __half g_wq0[DIMSZ*DIMSZ], g_wq1[DIMSZ*DIMSZ];
__device__ __align__(16) __half g_wo0[DIMSZ*DIMSZ], g_wo1[DIMSZ*DIMSZ];

__device__ __forceinline__ float ex2(float x){float r;asm("ex2.approx.f32 %0,%1;":"=f"(r):"f"(x));return r;}
__device__ __forceinline__ u32 smem_u32(const void*p){u32 a;asm("{ .reg .u64 t; cvta.to.shared.u64 t,%1; cvt.u32.u64 %0,t; }":"=r"(a):"l"(p));return a;}
__device__ __forceinline__ u32 packh(__half lo,__half hi){return (u32)__half_as_ushort(lo)|((u32)__half_as_ushort(hi)<<16);}
__device__ __forceinline__ void split2h(float s,__half&a,__half&b){
    a=__float2half_rn(s); b=__float2half_rn(s-__half2float(a));
}
__device__ __forceinline__ void ldmx4(u32* r,u32 a){
    asm volatile("ldmatrix.sync.aligned.m8n8.x4.shared.b16 {%0,%1,%2,%3},[%4];"
        :"=r"(r[0]),"=r"(r[1]),"=r"(r[2]),"=r"(r[3]):"r"(a));
}
__device__ __forceinline__ void mma16816(float* c,const u32* a,const u32* b){
    asm volatile("mma.sync.aligned.m16n8k16.row.col.f32.f16.f16.f32 "
        "{%0,%1,%2,%3},{%4,%5,%6,%7},{%8,%9},{%0,%1,%2,%3};"
        :"+f"(c[0]),"+f"(c[1]),"+f"(c[2]),"+f"(c[3])
        :"r"(a[0]),"r"(a[1]),"r"(a[2]),"r"(a[3]),"r"(b[0]),"r"(b[1]));
}
__device__ __forceinline__ void cpasync16(u32 dst,const void* src){
    asm volatile("cp.async.cg.shared.global [%0],[%1],16;"::"r"(dst),"l"(src));
}
#define CP_COMMIT() asm volatile("cp.async.commit_group;":::"memory")
#define CP_WAIT(n)  asm volatile("cp.async.wait_group %0;"::"n"(n):"memory")

// ---------------- prep ----------------
__global__ void split2h_kernel(const float* __restrict__ src,
                               __half* __restrict__ d0,__half* __restrict__ d1){
    size_t i2=((size_t)blockIdx.x*256+threadIdx.x)*2;
    float2 v=*(const float2*)(src+i2);
    __half x0,x1,y0,y1;
    split2h(v.x,x0,x1); split2h(v.y,y0,y1);
    *(u32*)&d0[i2]=packh(x0,y0);
    *(u32*)&d1[i2]=packh(x1,y1);
}
__global__ void mem_split_kernel(const float* __restrict__ mem){
    int i=blockIdx.x*256+threadIdx.x;
    if(i>=MROWS*HD) return;
    int m=i>>6, d=i&63;
    __half b0,b1; split2h(mem[i],b0,b1);
    g_k0[i]=b0; g_k1[i]=b1;
    g_vT0[d*MROWS+m]=b0; g_vT1[d*MROWS+m]=b1;
}

// ---------------- linear: 2x2 fp16 planes, 4 products (R15-proven) ----------------
#define SMEM_L 65536
__global__ void __launch_bounds__(256,2)
linear4_kernel(const __half* __restrict__ a0,const __half* __restrict__ a1,
               const __half* __restrict__ w0,const __half* __restrict__ w1,
               const float* __restrict__ bias,float* __restrict__ outp,int mode){
    extern __shared__ char smc[];
    const u32 sb=smem_u32(smc);
    const int tid=threadIdx.x, wid=tid>>5, lane=tid&31;
    const int i0=blockIdx.y*128, j0=blockIdx.x*128;

    float sacc[16][4];
    #pragma unroll
    for(int n=0;n<16;n++){sacc[n][0]=0;sacc[n][1]=0;sacc[n][2]=0;sacc[n][3]=0;}

    const int arow=wid*16+(lane&15);
    const u32 arow128=(u32)(arow*128);
    const int arx=arow&7, acs=lane>>4;
    const int browB=((lane>>4)<<3)+(lane&7);
    const int kcB=(lane>>3)&1;

    for(int kc=0;kc<16;kc++){
        __syncthreads();
        {
            const __half* ga[2]={a0,a1};
            const __half* gw[2]={w0,w1};
            #pragma unroll
            for(int s=0;s<2;s++)
                #pragma unroll
                for(int j=0;j<4;j++){
                    int idx=tid+256*j, row=idx>>3, cc=idx&7;
                    u32 so=(u32)(row*128+((cc^(row&7))<<4));
                    *(uint4*)(smc+s*16384+so)
                        =*(const uint4*)(ga[s]+(size_t)(i0+row)*DIMSZ+kc*64+cc*8);
                    *(uint4*)(smc+32768+s*16384+so)
                        =*(const uint4*)(gw[s]+(size_t)(j0+row)*DIMSZ+kc*64+cc*8);
                }
        }
        __syncthreads();
        #pragma unroll
        for(int kt=0;kt<4;kt++){
            u32 aq[2][4];
            const u32 ca=arow128+(u32)(((kt*2+acs)^arx)<<4);
            ldmx4(aq[0],sb+ca);
            ldmx4(aq[1],sb+16384+ca);
            #pragma unroll
            for(int ntp=0;ntp<8;ntp++){
                const int rowB=ntp*16+browB;
                const u32 offB=(u32)(rowB*128)+(u32)(((kt*2+kcB)^(rowB&7))<<4);
                float* s0=sacc[2*ntp]; float* s1=sacc[2*ntp+1];
                u32 bh[4],bl[4];
                ldmx4(bh,sb+32768+offB);
                ldmx4(bl,sb+49152+offB);
                mma16816(s0,aq[0],bh);   mma16816(s0,aq[1],bh);
                mma16816(s0,aq[0],bl);   mma16816(s0,aq[1],bl);
                mma16816(s1,aq[0],bh+2); mma16816(s1,aq[1],bh+2);
                mma16816(s1,aq[0],bl+2); mma16816(s1,aq[1],bl+2);
            }
        }
    }

    const int ra=i0+wid*16+(lane>>2), rb=ra+8;
    #pragma unroll
    for(int nt=0;nt<16;nt++){
        const int j=j0+nt*8+2*(lane&3);
        float2 bv=*(const float2*)(bias+j);
        if(mode==0){
            float v0=(sacc[nt][0]+bv.x)*SCALE_LOG2;
            float v1=(sacc[nt][1]+bv.y)*SCALE_LOG2;
            float v2=(sacc[nt][2]+bv.x)*SCALE_LOG2;
            float v3=(sacc[nt][3]+bv.y)*SCALE_LOG2;
            __half p0,p1,q0,q1;
            split2h(v0,p0,p1); split2h(v1,q0,q1);
            *(u32*)&g_q0[(size_t)ra*DIMSZ+j]=packh(p0,q0);
            *(u32*)&g_q1[(size_t)ra*DIMSZ+j]=packh(p1,q1);
            split2h(v2,p0,p1); split2h(v3,q0,q1);
            *(u32*)&g_q0[(size_t)rb*DIMSZ+j]=packh(p0,q0);
            *(u32*)&g_q1[(size_t)rb*DIMSZ+j]=packh(p1,q1);
        }else{
            *(float2*)(outp+(size_t)ra*DIMSZ+j)
                =make_float2(sacc[nt][0]*INV_SCALE+bv.x,sacc[nt][1]*INV_SCALE+bv.y);
            *(float2*)(outp+(size_t)rb*DIMSZ+j)
                =make_float2(sacc[nt][2]*INV_SCALE+bv.x,sacc[nt][3]*INV_SCALE+bv.y);
        }
    }
}

// ---------------- fused double-iteration attention: 3-stage pipeline ----------------
#define BUFO(b) ((b)*32768)
#define SMEM_AT 98304

__global__ void __launch_bounds__(256,2)
hopfield2_kernel(){
    extern __shared__ char smc[];
    const u32 sb=smem_u32(smc);
    const int tid=threadIdx.x, wid=tid>>5, lane=tid&31;
    const int h=blockIdx.y, r0=blockIdx.x*128;

    const int arow=wid*16+(lane&15);
    const u32 arow128=(u32)(arow*128);
    const int arx=arow&7, acs=lane>>4;
    const int browB=((lane>>4)<<3)+(lane&7);
    const int kcB=(lane>>3)&1;

    // ---- stage q0,q1 once; fragments live in registers across both iters ----
    u32 aqh[4][4], aql[4][4];
    #pragma unroll
    for(int j=0;j<4;j++){
        int idx=tid+256*j, row=idx>>3, c=idx&7;
        *(uint4*)(smc+row*128+((c^(row&7))<<4))
            =*(const uint4*)(g_q0+(size_t)(r0+row)*DIMSZ+h*HD+c*8);
    }
    __syncthreads();
    #pragma unroll
    for(int kt=0;kt<4;kt++) ldmx4(aqh[kt],sb+arow128+(u32)(((kt*2+acs)^arx)<<4));
    __syncthreads();
    #pragma unroll
    for(int j=0;j<4;j++){
        int idx=tid+256*j, row=idx>>3, c=idx&7;
        *(uint4*)(smc+row*128+((c^(row&7))<<4))
            =*(const uint4*)(g_q1+(size_t)(r0+row)*DIMSZ+h*HD+c*8);
    }
    __syncthreads();
    #pragma unroll
    for(int kt=0;kt<4;kt++) ldmx4(aql[kt],sb+arow128+(u32)(((kt*2+acs)^arx)<<4));
    __syncthreads();

    auto issue=[&](int c,u32 bofs){
        const __half* gk[2]={g_k0,g_k1};
        #pragma unroll
        for(int s=0;s<2;s++)
            #pragma unroll
            for(int j=0;j<2;j++){
                int idx=tid+256*j, row=idx>>3, cc=idx&7;
                cpasync16(sb+bofs+(u32)(s*8192+row*128+((cc^(row&7))<<4)),
                          gk[s]+(size_t)(c*MC+row)*HD+cc*8);
            }
        const __half* gv[2]={g_vT0,g_vT1};
        #pragma unroll
        for(int s=0;s<2;s++)
            #pragma unroll
            for(int j=0;j<2;j++){
                int idx=tid+256*j, row=idx>>3, cc=idx&7;
                cpasync16(sb+bofs+(u32)(16384+s*8192+row*128+((cc^(row&7))<<4)),
                          gv[s]+(size_t)row*MROWS+c*MC+cc*8);
            }
    };

    float oacc[8][4];
    float ma,mb,la,lb;

    for(int it=0;it<2;it++){
        ma=-1e30f; mb=-1e30f; la=0.0f; lb=0.0f;
        #pragma unroll
        for(int i=0;i<8;i++){oacc[i][0]=0;oacc[i][1]=0;oacc[i][2]=0;oacc[i][3]=0;}

        issue(0,BUFO(0)); CP_COMMIT();
        issue(1,BUFO(1)); CP_COMMIT();

        for(int c=0;c<NCH;c++){
            if(c+1<NCH) CP_WAIT(1); else CP_WAIT(0);
            __syncthreads();   // chunk-c data visible; also proves buf[(c+2)%3] free

            if(c+2<NCH){ issue(c+2,BUFO((c+2)%3)); CP_COMMIT(); }

            const u32 kb=sb+BUFO(c%3);

            // ---- S = Q@K^T: hh + lh + hl ----
            float sacc[8][4];
            #pragma unroll
            for(int i=0;i<8;i++){sacc[i][0]=0;sacc[i][1]=0;sacc[i][2]=0;sacc[i][3]=0;}
            #pragma unroll
            for(int kt=0;kt<4;kt++){
                #pragma unroll
                for(int ntp=0;ntp<4;ntp++){
                    const int rowB=ntp*16+browB;
                    const u32 offB=(u32)(rowB*128)+(u32)((((kt*2+kcB))^(rowB&7))<<4);
                    u32 bh[4],bl[4];
                    ldmx4(bh,kb+offB);
                    ldmx4(bl,kb+8192+offB);
                    float* s0=sacc[2*ntp]; float* s1=sacc[2*ntp+1];
                    mma16816(s0,aqh[kt],bh);   mma16816(s0,aql[kt],bh);   mma16816(s0,aqh[kt],bl);
                    mma16816(s1,aqh[kt],bh+2); mma16816(s1,aql[kt],bh+2); mma16816(s1,aqh[kt],bl+2);
                }
            }

            // ---- online softmax (base 2) ----
            float mxa=-1e30f,mxb=-1e30f;
            #pragma unroll
            for(int nt=0;nt<8;nt++){
                mxa=fmaxf(mxa,fmaxf(sacc[nt][0],sacc[nt][1]));
                mxb=fmaxf(mxb,fmaxf(sacc[nt][2],sacc[nt][3]));
            }
            mxa=fmaxf(mxa,__shfl_xor_sync(0xffffffffu,mxa,1));
            mxa=fmaxf(mxa,__shfl_xor_sync(0xffffffffu,mxa,2));
            mxb=fmaxf(mxb,__shfl_xor_sync(0xffffffffu,mxb,1));
            mxb=fmaxf(mxb,__shfl_xor_sync(0xffffffffu,mxb,2));
            float rsa=0.0f, rsb=0.0f;
            if(mxa>ma){
                float mna=mxa;
                float ala=ex2(ma-mna);
                ma=mna;
                la*=ala;
                #pragma unroll
                for(int dt=0;dt<8;dt++){ oacc[dt][0]*=ala; oacc[dt][1]*=ala; }
            }
            if(mxb>mb){
                float mnb=mxb;
                float alb=ex2(mb-mnb);
                mb=mnb;
                lb*=alb;
                #pragma unroll
                for(int dt=0;dt<8;dt++){ oacc[dt][2]*=alb; oacc[dt][3]*=alb; }
            }
            #pragma unroll
            for(int nt=0;nt<8;nt++){
                sacc[nt][0]=ex2(sacc[nt][0]-ma);
                sacc[nt][1]=ex2(sacc[nt][1]-ma);
                sacc[nt][2]=ex2(sacc[nt][2]-mb);
                sacc[nt][3]=ex2(sacc[nt][3]-mb);
                rsa+=sacc[nt][0]+sacc[nt][1];
                rsb+=sacc[nt][2]+sacc[nt][3];
            }
            rsa+=__shfl_xor_sync(0xffffffffu,rsa,1);
            rsa+=__shfl_xor_sync(0xffffffffu,rsa,2);
            rsb+=__shfl_xor_sync(0xffffffffu,rsb,1);
            rsb+=__shfl_xor_sync(0xffffffffu,rsb,2);
            la+=rsa; lb+=rsb;

            // ---- PV per kt: O += PhVh + PlVh + PhVl ----
            #pragma unroll
            for(int kt=0;kt<4;kt++){
                u32 ph[4], pl[4];
                #pragma unroll
                for(int half=0;half<2;half++){
                    const int nt=2*kt+half;
                    #pragma unroll
                    for(int rr=0;rr<2;rr++){
                        float p0=sacc[nt][rr*2], p1=sacc[nt][rr*2+1];
                        __half h0,l0,h1,l1;
                        split2h(p0,h0,l0); split2h(p1,h1,l1);
                        ph[half*2+rr]=packh(h0,h1);
                        pl[half*2+rr]=packh(l0,l1);
                    }
                }
                #pragma unroll
                for(int dtp=0;dtp<4;dtp++){
                    const int rowB=dtp*16+browB;
                    const u32 offV=(u32)(rowB*128)+(u32)((((kt*2+kcB))^(rowB&7))<<4);
                    u32 vh[4],vl[4];
                    ldmx4(vh,kb+16384+offV);
                    ldmx4(vl,kb+24576+offV);
                    float* o0=oacc[2*dtp]; float* o1=oacc[2*dtp+1];
                    mma16816(o0,ph,vh);   mma16816(o0,pl,vh);   mma16816(o0,ph,vl);
                    mma16816(o1,ph,vh+2); mma16816(o1,pl,vh+2); mma16816(o1,ph,vl+2);
                }
            }
            // no end-of-chunk barrier: reuse distance 3 + top barrier covers it
        }

        if(it==0){
            // ---- convert O -> next-iteration Q fragments, in registers ----
            const float sa=SCALE_LOG2/la, sb2=SCALE_LOG2/lb;
            #pragma unroll
            for(int kt=0;kt<4;kt++){
                #pragma unroll
                for(int half=0;half<2;half++){
                    const int nt=2*kt+half;
                    #pragma unroll
                    for(int rr=0;rr<2;rr++){
                        const float sc=(rr==0)?sa:sb2;
                        float v0=oacc[nt][rr*2]*sc, v1=oacc[nt][rr*2+1]*sc;
                        __half h0,l0,h1,l1;
                        split2h(v0,h0,l0); split2h(v1,h1,l1);
                        aqh[kt][half*2+rr]=packh(h0,h1);
                        aql[kt][half*2+rr]=packh(l0,l1);
                    }
                }
            }
            __syncthreads();   // all reads of last iter-0 buffers done before iter-1 reissues
        }
    }

    { // final epilogue: scaled q planes for the Wo linear
        const float sa=SCALE_LOG2/la, sb2=SCALE_LOG2/lb;
        const int qa=r0+wid*16+(lane>>2), qb=qa+8;
        const size_t basea=(size_t)qa*DIMSZ+h*HD, baseb=(size_t)qb*DIMSZ+h*HD;
        #pragma unroll
        for(int dt=0;dt<8;dt++){
            const int d=dt*8+2*(lane&3);
            float v0=oacc[dt][0]*sa, v1=oacc[dt][1]*sa;
            float v2=oacc[dt][2]*sb2, v3=oacc[dt][3]*sb2;
            __half x0,x1,y0,y1;
            split2h(v0,x0,x1); split2h(v1,y0,y1);
            *(u32*)&g_q0[basea+d]=packh(x0,y0);
            *(u32*)&g_q1[basea+d]=packh(x1,y1);
            split2h(v2,x0,x1); split2h(v3,y0,y1);
            *(u32*)&g_q0[baseb+d]=packh(x0,y0);
            *(u32*)&g_q1[baseb+d]=packh(x1,y1);
        }
    }
}

extern "C" void kernel_launch(void* const* d_in, const int* in_sizes, int n_in,
                              void* d_out, int out_size){
    (void)in_sizes;(void)n_in;(void)out_size;
    const float* x=(const float*)d_in[0];
    const float* mem=(const float*)d_in[1];
    const float* Wq=(const float*)d_in[2];
    const float* bq=(const float*)d_in[3];
    const float* Wo=(const float*)d_in[4];
    const float* bo=(const float*)d_in[5];
    float* out=(float*)d_out;

    __half *x0,*x1,*wq0,*wq1,*wo0,*wo1,*q0,*q1;
    cudaGetSymbolAddress((void**)&x0,g_x0);  cudaGetSymbolAddress((void**)&x1,g_x1);
    cudaGetSymbolAddress((void**)&wq0,g_wq0);cudaGetSymbolAddress((void**)&wq1,g_wq1);
    cudaGetSymbolAddress((void**)&wo0,g_wo0);cudaGetSymbolAddress((void**)&wo1,g_wo1);
    cudaGetSymbolAddress((void**)&q0,g_q0);  cudaGetSymbolAddress((void**)&q1,g_q1);

    cudaFuncSetAttribute(hopfield2_kernel,cudaFuncAttributeMaxDynamicSharedMemorySize,SMEM_AT);
    cudaFuncSetAttribute(linear4_kernel,cudaFuncAttributeMaxDynamicSharedMemorySize,SMEM_L);

    dim3 lg(DIMSZ/128,BL/128), ag(BL/128,NHEADS);

    mem_split_kernel<<<(MROWS*HD+255)/256,256>>>(mem);
    split2h_kernel<<<(u32)((size_t)BL*DIMSZ/2/256),256>>>(x,x0,x1);
    split2h_kernel<<<DIMSZ*DIMSZ/2/256,256>>>(Wq,wq0,wq1);
    split2h_kernel<<<DIMSZ*DIMSZ/2/256,256>>>(Wo,wo0,wo1);
    linear4_kernel<<<lg,256,SMEM_L>>>(x0,x1,wq0,wq1,bq,nullptr,0);
    hopfield2_kernel<<<ag,256,SMEM_AT>>>();
    linear4_kernel<<<lg,256,SMEM_L>>>(q0,q1,wo0,wo1,bo,out,1);
}

// round 17
// speedup vs baseline: 1.0126x; 1.0126x over previous
#include <cuda_runtime.h>
#include <cuda_fp16.h>
#include <cstdint>
#include <cstddef>

#define DIMSZ 1024
#define HD 64
#define NHEADS 16
#define BL 4096
#define MROWS 2048
#define MC 64
#define NCH (MROWS/MC)
#define SCALE_LOG2 23.083120654223414f
#define INV_SCALE  (1.0f/SCALE_LOG2)

typedef uint32_t u32;

__device__ __align__(16) __half g_k0[MROWS*HD], g_k1[MROWS*HD];
__device__ __align__(16) __half g_vT0[HD*MROWS], g_vT1[HD*MROWS];
__device__ __align__(16) __half g_q0[(size_t)BL*DIMSZ], g_q1[(size_t)BL*DIMSZ];
__device__ __align__(16) __half g_x0[(size_t)BL*DIMSZ], g_x1[(size_t)BL*DIMSZ];
__device__ __align__(16) __half g_wq0[DIMSZ*DIMSZ], g_wq1[DIMSZ*DIMSZ];
__device__ __align__(16) __half g_wo0[DIMSZ*DIMSZ], g_wo1[DIMSZ*DIMSZ];

__device__ __forceinline__ float ex2(float x){float r;asm("ex2.approx.f32 %0,%1;":"=f"(r):"f"(x));return r;}
__device__ __forceinline__ u32 smem_u32(const void*p){u32 a;asm("{ .reg .u64 t; cvta.to.shared.u64 t,%1; cvt.u32.u64 %0,t; }":"=r"(a):"l"(p));return a;}
__device__ __forceinline__ u32 packh(__half lo,__half hi){return (u32)__half_as_ushort(lo)|((u32)__half_as_ushort(hi)<<16);}
__device__ __forceinline__ void split2h(float s,__half&a,__half&b){
    a=__float2half_rn(s); b=__float2half_rn(s-__half2float(a));
}
__device__ __forceinline__ void ldmx4(u32* r,u32 a){
    asm volatile("ldmatrix.sync.aligned.m8n8.x4.shared.b16 {%0,%1,%2,%3},[%4];"
        :"=r"(r[0]),"=r"(r[1]),"=r"(r[2]),"=r"(r[3]):"r"(a));
}
__device__ __forceinline__ void mma16816(float* c,const u32* a,const u32* b){
    asm volatile("mma.sync.aligned.m16n8k16.row.col.f32.f16.f16.f32 "
        "{%0,%1,%2,%3},{%4,%5,%6,%7},{%8,%9},{%0,%1,%2,%3};"
        :"+f"(c[0]),"+f"(c[1]),"+f"(c[2]),"+f"(c[3])
        :"r"(a[0]),"r"(a[1]),"r"(a[2]),"r"(a[3]),"r"(b[0]),"r"(b[1]));
}
__device__ __forceinline__ void cpasync16(u32 dst,const void* src){
    asm volatile("cp.async.cg.shared.global [%0],[%1],16;"::"r"(dst),"l"(src));
}
#define CP_COMMIT() asm volatile("cp.async.commit_group;":::"memory")
#define CP_WAIT(n)  asm volatile("cp.async.wait_group %0;"::"n"(n):"memory")

// ---------------- prep ----------------
__global__ void split2h_kernel(const float* __restrict__ src,
                               __half* __restrict__ d0,__half* __restrict__ d1){
    size_t i2=((size_t)blockIdx.x*256+threadIdx.x)*2;
    float2 v=*(const float2*)(src+i2);
    __half x0,x1,y0,y1;
    split2h(v.x,x0,x1); split2h(v.y,y0,y1);
    *(u32*)&d0[i2]=packh(x0,y0);
    *(u32*)&d1[i2]=packh(x1,y1);
}
__global__ void mem_split_kernel(const float* __restrict__ mem){
    int i=blockIdx.x*256+threadIdx.x;
    if(i>=MROWS*HD) return;
    int m=i>>6, d=i&63;
    __half b0,b1; split2h(mem[i],b0,b1);
    g_k0[i]=b0; g_k1[i]=b1;
    g_vT0[d*MROWS+m]=b0; g_vT1[d*MROWS+m]=b1;
}

// ---------------- linear: 2x2 fp16 planes, 4 products (R15-proven) ----------------
#define SMEM_L 65536
__global__ void __launch_bounds__(256,2)
linear4_kernel(const __half* __restrict__ a0,const __half* __restrict__ a1,
               const __half* __restrict__ w0,const __half* __restrict__ w1,
               const float* __restrict__ bias,float* __restrict__ outp,int mode){
    extern __shared__ char smc[];
    const u32 sb=smem_u32(smc);
    const int tid=threadIdx.x, wid=tid>>5, lane=tid&31;
    const int i0=blockIdx.y*128, j0=blockIdx.x*128;

    float sacc[16][4];
    #pragma unroll
    for(int n=0;n<16;n++){sacc[n][0]=0;sacc[n][1]=0;sacc[n][2]=0;sacc[n][3]=0;}

    const int arow=wid*16+(lane&15);
    const u32 arow128=(u32)(arow*128);
    const int arx=arow&7, acs=lane>>4;
    const int browB=((lane>>4)<<3)+(lane&7);
    const int kcB=(lane>>3)&1;

    for(int kc=0;kc<16;kc++){
        __syncthreads();
        {
            const __half* ga[2]={a0,a1};
            const __half* gw[2]={w0,w1};
            #pragma unroll
            for(int s=0;s<2;s++)
                #pragma unroll
                for(int j=0;j<4;j++){
                    int idx=tid+256*j, row=idx>>3, cc=idx&7;
                    u32 so=(u32)(row*128+((cc^(row&7))<<4));
                    *(uint4*)(smc+s*16384+so)
                        =*(const uint4*)(ga[s]+(size_t)(i0+row)*DIMSZ+kc*64+cc*8);
                    *(uint4*)(smc+32768+s*16384+so)
                        =*(const uint4*)(gw[s]+(size_t)(j0+row)*DIMSZ+kc*64+cc*8);
                }
        }
        __syncthreads();
        #pragma unroll
        for(int kt=0;kt<4;kt++){
            u32 aq[2][4];
            const u32 ca=arow128+(u32)(((kt*2+acs)^arx)<<4);
            ldmx4(aq[0],sb+ca);
            ldmx4(aq[1],sb+16384+ca);
            #pragma unroll
            for(int ntp=0;ntp<8;ntp++){
                const int rowB=ntp*16+browB;
                const u32 offB=(u32)(rowB*128)+(u32)(((kt*2+kcB)^(rowB&7))<<4);
                float* s0=sacc[2*ntp]; float* s1=sacc[2*ntp+1];
                u32 bh[4],bl[4];
                ldmx4(bh,sb+32768+offB);
                ldmx4(bl,sb+49152+offB);
                mma16816(s0,aq[0],bh);   mma16816(s0,aq[1],bh);
                mma16816(s0,aq[0],bl);   mma16816(s0,aq[1],bl);
                mma16816(s1,aq[0],bh+2); mma16816(s1,aq[1],bh+2);
                mma16816(s1,aq[0],bl+2); mma16816(s1,aq[1],bl+2);
            }
        }
    }

    const int ra=i0+wid*16+(lane>>2), rb=ra+8;
    #pragma unroll
    for(int nt=0;nt<16;nt++){
        const int j=j0+nt*8+2*(lane&3);
        float2 bv=*(const float2*)(bias+j);
        if(mode==0){
            float v0=(sacc[nt][0]+bv.x)*SCALE_LOG2;
            float v1=(sacc[nt][1]+bv.y)*SCALE_LOG2;
            float v2=(sacc[nt][2]+bv.x)*SCALE_LOG2;
            float v3=(sacc[nt][3]+bv.y)*SCALE_LOG2;
            __half p0,p1,q0,q1;
            split2h(v0,p0,p1); split2h(v1,q0,q1);
            *(u32*)&g_q0[(size_t)ra*DIMSZ+j]=packh(p0,q0);
            *(u32*)&g_q1[(size_t)ra*DIMSZ+j]=packh(p1,q1);
            split2h(v2,p0,p1); split2h(v3,q0,q1);
            *(u32*)&g_q0[(size_t)rb*DIMSZ+j]=packh(p0,q0);
            *(u32*)&g_q1[(size_t)rb*DIMSZ+j]=packh(p1,q1);
        }else{
            *(float2*)(outp+(size_t)ra*DIMSZ+j)
                =make_float2(sacc[nt][0]*INV_SCALE+bv.x,sacc[nt][1]*INV_SCALE+bv.y);
            *(float2*)(outp+(size_t)rb*DIMSZ+j)
                =make_float2(sacc[nt][2]*INV_SCALE+bv.x,sacc[nt][3]*INV_SCALE+bv.y);
        }
    }
}

// ---------------- fused double-iteration attention: 3-stage pipeline,
//                  branch-free softmax (R15 math), 1 barrier/chunk ------------
#define BUFO(b) ((b)*32768)
#define SMEM_AT 98304

__global__ void __launch_bounds__(256,2)
hopfield2_kernel(){
    extern __shared__ char smc[];
    const u32 sb=smem_u32(smc);
    const int tid=threadIdx.x, wid=tid>>5, lane=tid&31;
    const int h=blockIdx.y, r0=blockIdx.x*128;

    const int arow=wid*16+(lane&15);
    const u32 arow128=(u32)(arow*128);
    const int arx=arow&7, acs=lane>>4;
    const int browB=((lane>>4)<<3)+(lane&7);
    const int kcB=(lane>>3)&1;

    // ---- stage q0,q1 once; fragments live in registers across both iters ----
    u32 aqh[4][4], aql[4][4];
    #pragma unroll
    for(int j=0;j<4;j++){
        int idx=tid+256*j, row=idx>>3, c=idx&7;
        *(uint4*)(smc+row*128+((c^(row&7))<<4))
            =*(const uint4*)(g_q0+(size_t)(r0+row)*DIMSZ+h*HD+c*8);
    }
    __syncthreads();
    #pragma unroll
    for(int kt=0;kt<4;kt++) ldmx4(aqh[kt],sb+arow128+(u32)(((kt*2+acs)^arx)<<4));
    __syncthreads();
    #pragma unroll
    for(int j=0;j<4;j++){
        int idx=tid+256*j, row=idx>>3, c=idx&7;
        *(uint4*)(smc+row*128+((c^(row&7))<<4))
            =*(const uint4*)(g_q1+(size_t)(r0+row)*DIMSZ+h*HD+c*8);
    }
    __syncthreads();
    #pragma unroll
    for(int kt=0;kt<4;kt++) ldmx4(aql[kt],sb+arow128+(u32)(((kt*2+acs)^arx)<<4));
    __syncthreads();

    auto issue=[&](int c,u32 bofs){
        const __half* gk[2]={g_k0,g_k1};
        #pragma unroll
        for(int s=0;s<2;s++)
            #pragma unroll
            for(int j=0;j<2;j++){
                int idx=tid+256*j, row=idx>>3, cc=idx&7;
                cpasync16(sb+bofs+(u32)(s*8192+row*128+((cc^(row&7))<<4)),
                          gk[s]+(size_t)(c*MC+row)*HD+cc*8);
            }
        const __half* gv[2]={g_vT0,g_vT1};
        #pragma unroll
        for(int s=0;s<2;s++)
            #pragma unroll
            for(int j=0;j<2;j++){
                int idx=tid+256*j, row=idx>>3, cc=idx&7;
                cpasync16(sb+bofs+(u32)(16384+s*8192+row*128+((cc^(row&7))<<4)),
                          gv[s]+(size_t)row*MROWS+c*MC+cc*8);
            }
    };

    float oacc[8][4];
    float ma,mb,la,lb;

    for(int it=0;it<2;it++){
        ma=-1e30f; mb=-1e30f; la=0.0f; lb=0.0f;
        #pragma unroll
        for(int i=0;i<8;i++){oacc[i][0]=0;oacc[i][1]=0;oacc[i][2]=0;oacc[i][3]=0;}

        issue(0,BUFO(0)); CP_COMMIT();
        issue(1,BUFO(1)); CP_COMMIT();

        for(int c=0;c<NCH;c++){
            if(c+1<NCH) CP_WAIT(1); else CP_WAIT(0);
            __syncthreads();   // chunk-c data visible; proves buf[(c+2)%3] free

            if(c+2<NCH){ issue(c+2,BUFO((c+2)%3)); CP_COMMIT(); }

            const u32 kb=sb+BUFO(c%3);

            // ---- S = Q@K^T: hh + lh + hl ----
            float sacc[8][4];
            #pragma unroll
            for(int i=0;i<8;i++){sacc[i][0]=0;sacc[i][1]=0;sacc[i][2]=0;sacc[i][3]=0;}
            #pragma unroll
            for(int kt=0;kt<4;kt++){
                #pragma unroll
                for(int ntp=0;ntp<4;ntp++){
                    const int rowB=ntp*16+browB;
                    const u32 offB=(u32)(rowB*128)+(u32)((((kt*2+kcB))^(rowB&7))<<4);
                    u32 bh[4],bl[4];
                    ldmx4(bh,kb+offB);
                    ldmx4(bl,kb+8192+offB);
                    float* s0=sacc[2*ntp]; float* s1=sacc[2*ntp+1];
                    mma16816(s0,aqh[kt],bh);   mma16816(s0,aql[kt],bh);   mma16816(s0,aqh[kt],bl);
                    mma16816(s1,aqh[kt],bh+2); mma16816(s1,aql[kt],bh+2); mma16816(s1,aqh[kt],bl+2);
                }
            }

            // ---- online softmax (base 2), branch-free (R15 math) ----
            float mxa=-1e30f,mxb=-1e30f;
            #pragma unroll
            for(int nt=0;nt<8;nt++){
                mxa=fmaxf(mxa,fmaxf(sacc[nt][0],sacc[nt][1]));
                mxb=fmaxf(mxb,fmaxf(sacc[nt][2],sacc[nt][3]));
            }
            mxa=fmaxf(mxa,__shfl_xor_sync(0xffffffffu,mxa,1));
            mxa=fmaxf(mxa,__shfl_xor_sync(0xffffffffu,mxa,2));
            mxb=fmaxf(mxb,__shfl_xor_sync(0xffffffffu,mxb,1));
            mxb=fmaxf(mxb,__shfl_xor_sync(0xffffffffu,mxb,2));
            float mna=fmaxf(ma,mxa), mnb=fmaxf(mb,mxb);
            float ala=ex2(ma-mna), alb=ex2(mb-mnb);
            ma=mna; mb=mnb;
            float rsa=0.0f, rsb=0.0f;
            #pragma unroll
            for(int nt=0;nt<8;nt++){
                sacc[nt][0]=ex2(sacc[nt][0]-mna);
                sacc[nt][1]=ex2(sacc[nt][1]-mna);
                sacc[nt][2]=ex2(sacc[nt][2]-mnb);
                sacc[nt][3]=ex2(sacc[nt][3]-mnb);
                rsa+=sacc[nt][0]+sacc[nt][1];
                rsb+=sacc[nt][2]+sacc[nt][3];
            }
            rsa+=__shfl_xor_sync(0xffffffffu,rsa,1);
            rsa+=__shfl_xor_sync(0xffffffffu,rsa,2);
            rsb+=__shfl_xor_sync(0xffffffffu,rsb,1);
            rsb+=__shfl_xor_sync(0xffffffffu,rsb,2);
            la=la*ala+rsa; lb=lb*alb+rsb;
            #pragma unroll
            for(int dt=0;dt<8;dt++){
                oacc[dt][0]*=ala; oacc[dt][1]*=ala;
                oacc[dt][2]*=alb; oacc[dt][3]*=alb;
            }

            // ---- PV per kt: O += PhVh + PlVh + PhVl ----
            #pragma unroll
            for(int kt=0;kt<4;kt++){
                u32 ph[4], pl[4];
                #pragma unroll
                for(int half=0;half<2;half++){
                    const int nt=2*kt+half;
                    #pragma unroll
                    for(int rr=0;rr<2;rr++){
                        float p0=sacc[nt][rr*2], p1=sacc[nt][rr*2+1];
                        __half h0,l0,h1,l1;
                        split2h(p0,h0,l0); split2h(p1,h1,l1);
                        ph[half*2+rr]=packh(h0,h1);
                        pl[half*2+rr]=packh(l0,l1);
                    }
                }
                #pragma unroll
                for(int dtp=0;dtp<4;dtp++){
                    const int rowB=dtp*16+browB;
                    const u32 offV=(u32)(rowB*128)+(u32)((((kt*2+kcB))^(rowB&7))<<4);
                    u32 vh[4],vl[4];
                    ldmx4(vh,kb+16384+offV);
                    ldmx4(vl,kb+24576+offV);
                    float* o0=oacc[2*dtp]; float* o1=oacc[2*dtp+1];
                    mma16816(o0,ph,vh);   mma16816(o0,pl,vh);   mma16816(o0,ph,vl);
                    mma16816(o1,ph,vh+2); mma16816(o1,pl,vh+2); mma16816(o1,ph,vl+2);
                }
            }
            // no end-of-chunk barrier: reuse distance 3 + top barrier covers it
        }

        if(it==0){
            // ---- convert O -> next-iteration Q fragments, in registers ----
            const float sa=SCALE_LOG2/la, sb2=SCALE_LOG2/lb;
            #pragma unroll
            for(int kt=0;kt<4;kt++){
                #pragma unroll
                for(int half=0;half<2;half++){
                    const int nt=2*kt+half;
                    #pragma unroll
                    for(int rr=0;rr<2;rr++){
                        const float sc=(rr==0)?sa:sb2;
                        float v0=oacc[nt][rr*2]*sc, v1=oacc[nt][rr*2+1]*sc;
                        __half h0,l0,h1,l1;
                        split2h(v0,h0,l0); split2h(v1,h1,l1);
                        aqh[kt][half*2+rr]=packh(h0,h1);
                        aql[kt][half*2+rr]=packh(l0,l1);
                    }
                }
            }
            __syncthreads();   // iter-0 buffer reads done before iter-1 reissues
        }
    }

    { // final epilogue: scaled q planes for the Wo linear
        const float sa=SCALE_LOG2/la, sb2=SCALE_LOG2/lb;
        const int qa=r0+wid*16+(lane>>2), qb=qa+8;
        const size_t basea=(size_t)qa*DIMSZ+h*HD, baseb=(size_t)qb*DIMSZ+h*HD;
        #pragma unroll
        for(int dt=0;dt<8;dt++){
            const int d=dt*8+2*(lane&3);
            float v0=oacc[dt][0]*sa, v1=oacc[dt][1]*sa;
            float v2=oacc[dt][2]*sb2, v3=oacc[dt][3]*sb2;
            __half x0,x1,y0,y1;
            split2h(v0,x0,x1); split2h(v1,y0,y1);
            *(u32*)&g_q0[basea+d]=packh(x0,y0);
            *(u32*)&g_q1[basea+d]=packh(x1,y1);
            split2h(v2,x0,x1); split2h(v3,y0,y1);
            *(u32*)&g_q0[baseb+d]=packh(x0,y0);
            *(u32*)&g_q1[baseb+d]=packh(x1,y1);
        }
    }
}

extern "C" void kernel_launch(void* const* d_in, const int* in_sizes, int n_in,
                              void* d_out, int out_size){
    (void)in_sizes;(void)n_in;(void)out_size;
    const float* x=(const float*)d_in[0];
    const float* mem=(const float*)d_in[1];
    const float* Wq=(const float*)d_in[2];
    const float* bq=(const float*)d_in[3];
    const float* Wo=(const float*)d_in[4];
    const float* bo=(const float*)d_in[5];
    float* out=(float*)d_out;

    __half *x0,*x1,*wq0,*wq1,*wo0,*wo1,*q0,*q1;
    cudaGetSymbolAddress((void**)&x0,g_x0);  cudaGetSymbolAddress((void**)&x1,g_x1);
    cudaGetSymbolAddress((void**)&wq0,g_wq0);cudaGetSymbolAddress((void**)&wq1,g_wq1);
    cudaGetSymbolAddress((void**)&wo0,g_wo0);cudaGetSymbolAddress((void**)&wo1,g_wo1);
    cudaGetSymbolAddress((void**)&q0,g_q0);  cudaGetSymbolAddress((void**)&q1,g_q1);

    cudaFuncSetAttribute(hopfield2_kernel,cudaFuncAttributeMaxDynamicSharedMemorySize,SMEM_AT);
    cudaFuncSetAttribute(linear4_kernel,cudaFuncAttributeMaxDynamicSharedMemorySize,SMEM_L);

    dim3 lg(DIMSZ/128,BL/128), ag(BL/128,NHEADS);

    mem_split_kernel<<<(MROWS*HD+255)/256,256>>>(mem);
    split2h_kernel<<<(u32)((size_t)BL*DIMSZ/2/256),256>>>(x,x0,x1);
    split2h_kernel<<<DIMSZ*DIMSZ/2/256,256>>>(Wq,wq0,wq1);
    split2h_kernel<<<DIMSZ*DIMSZ/2/256,256>>>(Wo,wo0,wo1);
    linear4_kernel<<<lg,256,SMEM_L>>>(x0,x1,wq0,wq1,bq,nullptr,0);
    hopfield2_kernel<<<ag,256,SMEM_AT>>>();
    linear4_kernel<<<lg,256,SMEM_L>>>(q0,q1,wo0,wo1,bo,out,1);
}